// round 4
// baseline (speedup 1.0000x reference)
#include <cuda_runtime.h>

// Fully fused SAGPooling: one block per graph.
// Phases: (1) per-node dual dot products -> smem
//         (2) edge scatter-add via smem atomics (algebraic collapse of segment_sum @ w_rel)
//         (3) tanh scores -> exact top-k SET via rank counting (2 threads/node)
//         (4) weighted mean over selected rows (4 replicas, 8 accumulators)
//         (5) output projection (4-way split over d)
__global__ __launch_bounds__(1024, 1)
void k_fused(const float* __restrict__ x,
             const int* __restrict__ ei,
             const float* __restrict__ wrel,
             const float* __restrict__ brel,
             const float* __restrict__ wroot,
             const float* __restrict__ wproj,
             const float* __restrict__ bproj,
             float* __restrict__ out,
             int n, int k, int d, int odim, int E, int Eg, int pd) {
    extern __shared__ unsigned char sm[];
    unsigned long long* keys = (unsigned long long*)sm;          // n u64
    float* p_s    = (float*)(keys + n);                          // n
    float* r_s    = p_s + n;                                     // n
    float* agg_s  = r_s + n;                                     // n
    float* svals  = agg_s + n;                                   // k
    int*   sidx   = (int*)(svals + k);                           // k
    float* part   = (float*)(sidx + k);                          // 4*pd
    float* pooled = part + 4 * pd;                               // d
    int*   cnt    = (int*)(pooled + d);

    const int g    = blockIdx.x;
    const int t    = threadIdx.x;
    const int base = g * n;
    const int d4   = d >> 2;

    if (t == 0) *cnt = 0;

    // ---------------- Phase 1: p[i] = x_i . w_rel, r[i] = x_i . w_root -------
    {
        const float4* x4  = (const float4*)x;
        const float4* wa4 = (const float4*)wrel;
        const float4* wb4 = (const float4*)wroot;
        const int h   = t & 1;
        const int nt2 = blockDim.x >> 1;
        const int hw  = d4 >> 1;              // float4's per half
        const int c0  = h * hw, c1 = c0 + hw;
        for (int i = t >> 1; i < n; i += nt2) {
            const float4* xr = x4 + (size_t)(base + i) * d4;
            float s0 = 0.f, s1 = 0.f, q0 = 0.f, q1 = 0.f;
#pragma unroll 8
            for (int c = c0; c < c1; c += 2) {
                float4 xv = xr[c], xw = xr[c + 1];
                float4 a0 = wa4[c], a1 = wa4[c + 1];
                float4 b0 = wb4[c], b1 = wb4[c + 1];
                s0 += xv.x * a0.x + xv.y * a0.y + xv.z * a0.z + xv.w * a0.w;
                s1 += xw.x * a1.x + xw.y * a1.y + xw.z * a1.z + xw.w * a1.w;
                q0 += xv.x * b0.x + xv.y * b0.y + xv.z * b0.z + xv.w * b0.w;
                q1 += xw.x * b1.x + xw.y * b1.y + xw.z * b1.z + xw.w * b1.w;
            }
            float sp = s0 + s1, sr = q0 + q1;
            sp += __shfl_xor_sync(0xffffffffu, sp, 1);
            sr += __shfl_xor_sync(0xffffffffu, sr, 1);
            if (h == 0) { p_s[i] = sp; r_s[i] = sr; }
            else        { agg_s[i] = 0.f; }
        }
    }
    __syncthreads();

    // ---------------- Phase 2: smem edge scatter-add -------------------------
    {
        const int eb = g * Eg;
        for (int e = t; e < Eg; e += blockDim.x) {
            int s  = ei[eb + e] - base;          // local src
            int dd = ei[E + eb + e] - base;      // local dst
            atomicAdd(&agg_s[dd], p_s[s]);
        }
    }
    __syncthreads();

    // ---------------- Phase 3: tanh scores -> sortable keys ------------------
    const float br = brel[0];
    if (t < n) {
        float s = tanhf(agg_s[t] + br + r_s[t]);
        unsigned u = __float_as_uint(s);
        u = (u & 0x80000000u) ? ~u : (u | 0x80000000u);
        // low bits: n-1-i so smaller index wins ties (jax.lax.top_k order)
        keys[t] = ((unsigned long long)u << 32) | (unsigned)(n - 1 - t);
    }
    __syncthreads();

    // rank counting, 2 threads per node (each scans half the keys)
    {
        int i  = t >> 1;
        int hh = t & 1;
        int ic = i < n ? i : n - 1;              // clamp: keep warp converged
        unsigned long long my = keys[ic];
        int half = n >> 1;
        int j0 = hh * half, j1 = j0 + half;
        int rank = 0;
#pragma unroll 8
        for (int j = j0; j < j1; j++)
            rank += (keys[j] > my);
        rank += __shfl_xor_sync(0xffffffffu, rank, 1);
        if (i < n && hh == 0 && rank < k) {
            int pos = atomicAdd(cnt, 1);
            unsigned hu = (unsigned)(my >> 32);
            unsigned fu = (hu & 0x80000000u) ? (hu & 0x7fffffffu) : ~hu;
            svals[pos] = __uint_as_float(fu);
            sidx[pos]  = i;
        }
    }
    __syncthreads();

    // ---------------- Phase 4: weighted mean over selected rows --------------
    {
        const int col  = t % d;
        const int rep  = t / d;
        const int nrep = blockDim.x / d;
        const int per  = (k + nrep - 1) / nrep;
        const int j0   = rep * per;
        const int j1   = min(j0 + per, k);
        float a[8];
#pragma unroll
        for (int u = 0; u < 8; u++) a[u] = 0.f;
        int j = j0;
        for (; j + 8 <= j1; j += 8) {
#pragma unroll
            for (int u = 0; u < 8; u++)
                a[u] += svals[j + u] * x[(size_t)(base + sidx[j + u]) * d + col];
        }
        for (; j < j1; j++)
            a[0] += svals[j] * x[(size_t)(base + sidx[j]) * d + col];
        float s = 0.f;
#pragma unroll
        for (int u = 0; u < 8; u++) s += a[u];
        part[rep * pd + col] = s;
    }
    __syncthreads();

    if (t < d) {
        const int nrep = blockDim.x / d;
        float s = 0.f;
        for (int rr = 0; rr < nrep; rr++) s += part[rr * pd + t];
        pooled[t] = s / (float)k;
    }
    __syncthreads();

    // ---------------- Phase 5: projection ------------------------------------
    {
        const int o    = t % odim;
        const int p    = t / odim;
        const int nrep = blockDim.x / odim;
        const int per  = (d + nrep - 1) / nrep;
        const int d0   = p * per;
        const int d1   = min(d0 + per, d);
        float acc = 0.f;
        int dd = d0;
        for (; dd + 8 <= d1; dd += 8) {
#pragma unroll
            for (int u = 0; u < 8; u++)
                acc += pooled[dd + u] * wproj[(size_t)(dd + u) * odim + o];
        }
        for (; dd < d1; dd++)
            acc += pooled[dd] * wproj[(size_t)dd * odim + o];
        part[p * pd + o] = acc;
    }
    __syncthreads();

    if (t < odim) {
        const int nrep = blockDim.x / odim;
        float s = bproj[t];
        for (int rr = 0; rr < nrep; rr++) s += part[rr * pd + t];
        out[(size_t)g * odim + t] = s;
    }
}

// Inputs: x, edge_index, batch, num_graphs, w_rel, b_rel, w_root, w_proj, b_proj.
// Output: [B, out_dim] float32.
extern "C" void kernel_launch(void* const* d_in, const int* in_sizes, int n_in,
                              void* d_out, int out_size) {
    const float* x     = (const float*)d_in[0];
    const int*   ei    = (const int*)d_in[1];
    const float* wrel  = (const float*)d_in[4];
    const float* brel  = (const float*)d_in[5];
    const float* wroot = (const float*)d_in[6];
    const float* wproj = (const float*)d_in[7];
    const float* bproj = (const float*)d_in[8];
    float* out = (float*)d_out;

    const int odim = in_sizes[8];
    const int d    = in_sizes[7] / odim;
    const int N    = in_sizes[0] / d;
    const int E    = in_sizes[1] / 2;
    const int B    = out_size / odim;
    const int n    = N / B;
    const int k    = (n + 1) / 2;     // ceil(0.5 * n), RATIO = 0.5
    const int Eg   = E / B;           // edges per graph (contiguous blocks)
    const int pd   = d > odim ? d : odim;

    size_t smem = (size_t)n * 8      // keys
                + (size_t)n * 12     // p, r, agg
                + (size_t)k * 8      // svals + sidx
                + (size_t)pd * 16    // part (4 replicas)
                + (size_t)d * 4      // pooled
                + 16;                // cnt + pad

    k_fused<<<B, 1024, smem>>>(x, ei, wrel, brel, wroot, wproj, bproj, out,
                               n, k, d, odim, E, Eg, pd);
}

// round 5
// speedup vs baseline: 1.4104x; 1.4104x over previous
#include <cuda_runtime.h>

#define MAX_N 65536

__device__ float g_p[MAX_N];    // x . w_rel  per node
__device__ float g_r[MAX_N];    // x . w_root per node

// ---------------------------------------------------------------------------
// Kernel 1: per-node dual dot products. 8 lanes per node (4 nodes/warp),
// proven-coalesced layout (each LDG.128 touches 4 lines). Weights come from
// shared memory, eliminating 2/3 of global LDGs.
// ---------------------------------------------------------------------------
__global__ void k_scores(const float4* __restrict__ x4,
                         const float4* __restrict__ wrel4,
                         const float4* __restrict__ wroot4,
                         int N, int d4) {
    extern __shared__ float4 wsm[];          // [0,d4): wrel, [d4,2*d4): wroot
    int t = threadIdx.x;
    for (int c = t; c < 2 * d4; c += blockDim.x)
        wsm[c] = (c < d4) ? wrel4[c] : wroot4[c - d4];
    __syncthreads();
    const float4* wa = wsm;
    const float4* wb = wsm + d4;

    int warp = (blockIdx.x * blockDim.x + t) >> 5;
    int lane = t & 31;
    int sub  = lane >> 3;          // node within warp (0..3)
    int l8   = lane & 7;           // lane within node-segment
    int node = warp * 4 + sub;
    if (node >= N) return;

    const float4* xr = x4 + (size_t)node * d4;
    float sp = 0.f, sr = 0.f;
#pragma unroll 8
    for (int c = l8; c < d4; c += 8) {
        float4 xv = xr[c];
        float4 a  = wa[c];
        float4 b  = wb[c];
        sp += xv.x * a.x + xv.y * a.y + xv.z * a.z + xv.w * a.w;
        sr += xv.x * b.x + xv.y * b.y + xv.z * b.z + xv.w * b.w;
    }
#pragma unroll
    for (int o = 4; o; o >>= 1) {
        sp += __shfl_xor_sync(0xffffffffu, sp, o);
        sr += __shfl_xor_sync(0xffffffffu, sr, o);
    }
    if (l8 == 0) {
        g_p[node] = sp;
        g_r[node] = sr;
    }
}

// ---------------------------------------------------------------------------
// Kernel 2 (per-graph, 1024 threads): edge aggregation via SMEM atomics,
// tanh scores, exact top-k SET via rank counting, weighted mean gather,
// output projection.
// smem: [keys: n u64 | p: n | agg: n | svals: k | sidx: k | part: 4*pd | pooled: d | cnt]
// ---------------------------------------------------------------------------
__global__ __launch_bounds__(1024, 1)
void k_pool(const float* __restrict__ x,
            const int* __restrict__ ei,
            const float* __restrict__ brel,
            const float* __restrict__ wproj,
            const float* __restrict__ bproj,
            float* __restrict__ out,
            int n, int k, int d, int odim, int E, int Eg, int pd) {
    extern __shared__ unsigned char sm[];
    unsigned long long* keys = (unsigned long long*)sm;          // n
    float* p_s    = (float*)(keys + n);                          // n
    float* agg_s  = p_s + n;                                     // n
    float* svals  = agg_s + n;                                   // k
    int*   sidx   = (int*)(svals + k);                           // k
    float* part   = (float*)(sidx + k);                          // 4*pd
    float* pooled = part + 4 * pd;                               // d
    int*   cnt    = (int*)(pooled + d);

    const int g    = blockIdx.x;
    const int t    = threadIdx.x;
    const int base = g * n;

    if (t == 0) *cnt = 0;
    // load p for this graph, zero agg
    for (int i = t; i < n; i += blockDim.x) {
        p_s[i]   = g_p[base + i];
        agg_s[i] = 0.f;
    }
    __syncthreads();

    // ---- edge aggregation (graph-local, smem atomics) ----
    {
        const int eb = g * Eg;
        for (int e = t; e < Eg; e += blockDim.x) {
            int s  = ei[eb + e] - base;
            int dd = ei[E + eb + e] - base;
            atomicAdd(&agg_s[dd], p_s[s]);
        }
    }
    __syncthreads();

    // ---- tanh scores -> sortable keys ----
    const float br = brel[0];
    float myscore = 0.f;
    if (t < n) {
        myscore = tanhf(agg_s[t] + br + g_r[base + t]);
        unsigned u = __float_as_uint(myscore);
        u = (u & 0x80000000u) ? ~u : (u | 0x80000000u);
        // low bits: n-1-i so smaller index wins ties (jax.lax.top_k order)
        keys[t] = ((unsigned long long)u << 32) | (unsigned)(n - 1 - t);
    }
    __syncthreads();

    // ---- rank counting, 2 threads per node (each scans half the keys) ----
    {
        int i  = t >> 1;
        int hh = t & 1;
        int ic = i < n ? i : n - 1;              // clamp: keep warp converged
        unsigned long long my = keys[ic];
        int half = n >> 1;
        int j0 = hh * half, j1 = j0 + half;
        int rank = 0;
#pragma unroll 8
        for (int j = j0; j < j1; j++)
            rank += (keys[j] > my);
        rank += __shfl_xor_sync(0xffffffffu, rank, 1);
        if (i < n && hh == 0 && rank < k) {
            int pos = atomicAdd(cnt, 1);
            unsigned hu = (unsigned)(my >> 32);
            unsigned fu = (hu & 0x80000000u) ? (hu & 0x7fffffffu) : ~hu;
            svals[pos] = __uint_as_float(fu);
            sidx[pos]  = i;
        }
    }
    __syncthreads();

    // ---- weighted mean over selected rows (4 replicas x d cols, 8 accs) ----
    {
        const int col  = t % d;
        const int rep  = t / d;
        const int nrep = blockDim.x / d;
        const int per  = (k + nrep - 1) / nrep;
        const int j0   = rep * per;
        const int j1   = min(j0 + per, k);
        float a[8];
#pragma unroll
        for (int u = 0; u < 8; u++) a[u] = 0.f;
        int j = j0;
        for (; j + 8 <= j1; j += 8) {
#pragma unroll
            for (int u = 0; u < 8; u++)
                a[u] += svals[j + u] * x[(size_t)(base + sidx[j + u]) * d + col];
        }
        for (; j < j1; j++)
            a[0] += svals[j] * x[(size_t)(base + sidx[j]) * d + col];
        float s = 0.f;
#pragma unroll
        for (int u = 0; u < 8; u++) s += a[u];
        part[rep * pd + col] = s;
    }
    __syncthreads();

    if (t < d) {
        const int nrep = blockDim.x / d;
        float s = 0.f;
        for (int rr = 0; rr < nrep; rr++) s += part[rr * pd + t];
        pooled[t] = s / (float)k;
    }
    __syncthreads();

    // ---- projection: out[g,o] = b[o] + sum_dd pooled[dd]*wproj[dd,o] ----
    {
        const int o    = t % odim;
        const int p    = t / odim;
        const int nrep = blockDim.x / odim;
        const int per  = (d + nrep - 1) / nrep;
        const int d0   = p * per;
        const int d1   = min(d0 + per, d);
        float acc = 0.f;
        int dd = d0;
        for (; dd + 8 <= d1; dd += 8) {
#pragma unroll
            for (int u = 0; u < 8; u++)
                acc += pooled[dd + u] * wproj[(size_t)(dd + u) * odim + o];
        }
        for (; dd < d1; dd++)
            acc += pooled[dd] * wproj[(size_t)dd * odim + o];
        part[p * pd + o] = acc;
    }
    __syncthreads();

    if (t < odim) {
        const int nrep = blockDim.x / odim;
        float s = bproj[t];
        for (int rr = 0; rr < nrep; rr++) s += part[rr * pd + t];
        out[(size_t)g * odim + t] = s;
    }
}

// ---------------------------------------------------------------------------
// Inputs: x, edge_index, batch, num_graphs, w_rel, b_rel, w_root, w_proj, b_proj.
// Output: [B, out_dim] float32.
// ---------------------------------------------------------------------------
extern "C" void kernel_launch(void* const* d_in, const int* in_sizes, int n_in,
                              void* d_out, int out_size) {
    const float* x     = (const float*)d_in[0];
    const int*   ei    = (const int*)d_in[1];
    const float* wrel  = (const float*)d_in[4];
    const float* brel  = (const float*)d_in[5];
    const float* wroot = (const float*)d_in[6];
    const float* wproj = (const float*)d_in[7];
    const float* bproj = (const float*)d_in[8];
    float* out = (float*)d_out;

    const int odim = in_sizes[8];
    const int d    = in_sizes[7] / odim;
    const int N    = in_sizes[0] / d;
    const int E    = in_sizes[1] / 2;
    const int B    = out_size / odim;
    const int n    = N / B;
    const int k    = (n + 1) / 2;     // ceil(0.5 * n), RATIO = 0.5
    const int Eg   = E / B;           // edges per graph (contiguous blocks)
    const int pd   = d > odim ? d : odim;
    const int d4   = d / 4;

    // K1: 8 lanes per node (4 nodes/warp), weights in smem
    int warps = (N + 3) / 4;
    size_t smem1 = (size_t)(2 * d4) * sizeof(float4);
    k_scores<<<(warps * 32 + 255) / 256, 256, smem1>>>(
        (const float4*)x, (const float4*)wrel, (const float4*)wroot, N, d4);

    // K2: fused edges + select + pool + project, one block per graph
    size_t smem2 = (size_t)n * 8      // keys
                 + (size_t)n * 8      // p, agg
                 + (size_t)k * 8      // svals + sidx
                 + (size_t)pd * 16    // part
                 + (size_t)d * 4      // pooled
                 + 16;                // cnt + pad
    k_pool<<<B, 1024, smem2>>>(x, ei, brel, wproj, bproj, out,
                               n, k, d, odim, E, Eg, pd);
}

// round 6
// speedup vs baseline: 1.5122x; 1.0722x over previous
#include <cuda_runtime.h>

#define MAX_N 65536

__device__ float g_p[MAX_N];    // x . w_rel  per node
__device__ float g_r[MAX_N];    // x . w_root per node

// ---------------------------------------------------------------------------
// Kernel 1: per-node dual dot products. 8 lanes per node (4 nodes/warp),
// weights in shared memory (2/3 of global LDGs eliminated).
// ---------------------------------------------------------------------------
__global__ void k_scores(const float4* __restrict__ x4,
                         const float4* __restrict__ wrel4,
                         const float4* __restrict__ wroot4,
                         int N, int d4) {
    extern __shared__ float4 wsm[];          // [0,d4): wrel, [d4,2*d4): wroot
    int t = threadIdx.x;
    for (int c = t; c < 2 * d4; c += blockDim.x)
        wsm[c] = (c < d4) ? wrel4[c] : wroot4[c - d4];
    __syncthreads();
    const float4* wa = wsm;
    const float4* wb = wsm + d4;

    int warp = (blockIdx.x * blockDim.x + t) >> 5;
    int lane = t & 31;
    int sub  = lane >> 3;
    int l8   = lane & 7;
    int node = warp * 4 + sub;
    if (node >= N) return;

    const float4* xr = x4 + (size_t)node * d4;
    float sp = 0.f, sr = 0.f;
#pragma unroll 8
    for (int c = l8; c < d4; c += 8) {
        float4 xv = xr[c];
        float4 a  = wa[c];
        float4 b  = wb[c];
        sp += xv.x * a.x + xv.y * a.y + xv.z * a.z + xv.w * a.w;
        sr += xv.x * b.x + xv.y * b.y + xv.z * b.z + xv.w * b.w;
    }
#pragma unroll
    for (int o = 4; o; o >>= 1) {
        sp += __shfl_xor_sync(0xffffffffu, sp, o);
        sr += __shfl_xor_sync(0xffffffffu, sr, o);
    }
    if (l8 == 0) {
        g_p[node] = sp;
        g_r[node] = sr;
    }
}

// ---------------------------------------------------------------------------
// Kernel 2 (per-graph, 1024 threads): smem edge aggregation, tanh scores,
// exact top-k SET via rank counting, float4 weighted-mean gather, projection.
// smem: [keys: n u64 | p: n | agg: n | svals: k | sidx: k |
//        part: (1024/(d/4))*d f32 | pooled: d | cnt]
// ---------------------------------------------------------------------------
__global__ __launch_bounds__(1024, 1)
void k_pool(const float* __restrict__ x,
            const int* __restrict__ ei,
            const float* __restrict__ brel,
            const float* __restrict__ wproj,
            const float* __restrict__ bproj,
            float* __restrict__ out,
            int n, int k, int d, int odim, int E, int Eg, int nrep4) {
    extern __shared__ unsigned char sm[];
    unsigned long long* keys = (unsigned long long*)sm;          // n
    float* p_s    = (float*)(keys + n);                          // n
    float* agg_s  = p_s + n;                                     // n
    float* svals  = agg_s + n;                                   // k
    int*   sidx   = (int*)(svals + k);                           // k
    float* part   = (float*)(sidx + k);                          // nrep4 * d
    float* pooled = part + nrep4 * d;                            // d
    int*   cnt    = (int*)(pooled + d);

    const int g    = blockIdx.x;
    const int t    = threadIdx.x;
    const int base = g * n;

    if (t == 0) *cnt = 0;
    for (int i = t; i < n; i += blockDim.x) {
        p_s[i]   = g_p[base + i];
        agg_s[i] = 0.f;
    }
    __syncthreads();

    // ---- edge aggregation (graph-local, smem atomics) ----
    {
        const int eb = g * Eg;
        for (int e = t; e < Eg; e += blockDim.x) {
            int s  = ei[eb + e] - base;
            int dd = ei[E + eb + e] - base;
            atomicAdd(&agg_s[dd], p_s[s]);
        }
    }
    __syncthreads();

    // ---- tanh scores -> sortable keys (tanh BEFORE ranking: saturation to
    //      1.0f creates ties whose index-order tie-break must match reference)
    const float br = brel[0];
    if (t < n) {
        float s = tanhf(agg_s[t] + br + g_r[base + t]);
        unsigned u = __float_as_uint(s);
        u = (u & 0x80000000u) ? ~u : (u | 0x80000000u);
        keys[t] = ((unsigned long long)u << 32) | (unsigned)(n - 1 - t);
    }
    __syncthreads();

    // ---- rank counting, 2 threads per node ----
    {
        int i  = t >> 1;
        int hh = t & 1;
        int ic = i < n ? i : n - 1;
        unsigned long long my = keys[ic];
        int half = n >> 1;
        int j0 = hh * half, j1 = j0 + half;
        int rank = 0;
#pragma unroll 16
        for (int j = j0; j < j1; j++)
            rank += (keys[j] > my);
        rank += __shfl_xor_sync(0xffffffffu, rank, 1);
        if (i < n && hh == 0 && rank < k) {
            int pos = atomicAdd(cnt, 1);
            unsigned hu = (unsigned)(my >> 32);
            unsigned fu = (hu & 0x80000000u) ? (hu & 0x7fffffffu) : ~hu;
            svals[pos] = __uint_as_float(fu);
            sidx[pos]  = i;
        }
    }
    __syncthreads();

    // ---- weighted mean: float4 gather, nrep4 replicas over nodes ----
    {
        const int d4   = d >> 2;
        const int col4 = t % d4;
        const int rep  = t / d4;
        const int per  = (k + nrep4 - 1) / nrep4;
        const int j0   = rep * per;
        const int j1   = min(j0 + per, k);
        const float4* x4 = (const float4*)x;
        float4 a0 = {0,0,0,0}, a1 = {0,0,0,0}, a2 = {0,0,0,0}, a3 = {0,0,0,0};
        int j = j0;
        for (; j + 4 <= j1; j += 4) {
            float v0 = svals[j], v1 = svals[j+1], v2 = svals[j+2], v3 = svals[j+3];
            int   r0 = sidx[j],  r1 = sidx[j+1],  r2 = sidx[j+2],  r3 = sidx[j+3];
            float4 q0 = x4[(size_t)(base + r0) * d4 + col4];
            float4 q1 = x4[(size_t)(base + r1) * d4 + col4];
            float4 q2 = x4[(size_t)(base + r2) * d4 + col4];
            float4 q3 = x4[(size_t)(base + r3) * d4 + col4];
            a0.x += v0*q0.x; a0.y += v0*q0.y; a0.z += v0*q0.z; a0.w += v0*q0.w;
            a1.x += v1*q1.x; a1.y += v1*q1.y; a1.z += v1*q1.z; a1.w += v1*q1.w;
            a2.x += v2*q2.x; a2.y += v2*q2.y; a2.z += v2*q2.z; a2.w += v2*q2.w;
            a3.x += v3*q3.x; a3.y += v3*q3.y; a3.z += v3*q3.z; a3.w += v3*q3.w;
        }
        for (; j < j1; j++) {
            float v = svals[j];
            float4 q = x4[(size_t)(base + sidx[j]) * d4 + col4];
            a0.x += v*q.x; a0.y += v*q.y; a0.z += v*q.z; a0.w += v*q.w;
        }
        float4 s;
        s.x = a0.x + a1.x + a2.x + a3.x;
        s.y = a0.y + a1.y + a2.y + a3.y;
        s.z = a0.z + a1.z + a2.z + a3.z;
        s.w = a0.w + a1.w + a2.w + a3.w;
        ((float4*)part)[rep * d4 + col4] = s;
    }
    __syncthreads();

    if (t < d) {
        float s = 0.f;
        for (int rr = 0; rr < nrep4; rr++) s += part[rr * d + t];
        pooled[t] = s / (float)k;
    }
    __syncthreads();

    // ---- projection: out[g,o] = b[o] + sum_dd pooled[dd]*wproj[dd,o] ----
    {
        const int o    = t % odim;
        const int p    = t / odim;
        const int nrep = blockDim.x / odim;
        const int per  = (d + nrep - 1) / nrep;
        const int d0   = p * per;
        const int d1   = min(d0 + per, d);
        float acc = 0.f;
        int dd = d0;
        for (; dd + 8 <= d1; dd += 8) {
#pragma unroll
            for (int u = 0; u < 8; u++)
                acc += pooled[dd + u] * wproj[(size_t)(dd + u) * odim + o];
        }
        for (; dd < d1; dd++)
            acc += pooled[dd] * wproj[(size_t)dd * odim + o];
        part[p * odim + o] = acc;   // reuse part[] for projection partials
    }
    __syncthreads();

    if (t < odim) {
        const int nrep = blockDim.x / odim;
        float s = bproj[t];
        for (int rr = 0; rr < nrep; rr++) s += part[rr * odim + t];
        out[(size_t)g * odim + t] = s;
    }
}

// ---------------------------------------------------------------------------
// Inputs: x, edge_index, batch, num_graphs, w_rel, b_rel, w_root, w_proj, b_proj.
// Output: [B, out_dim] float32.
// ---------------------------------------------------------------------------
extern "C" void kernel_launch(void* const* d_in, const int* in_sizes, int n_in,
                              void* d_out, int out_size) {
    const float* x     = (const float*)d_in[0];
    const int*   ei    = (const int*)d_in[1];
    const float* wrel  = (const float*)d_in[4];
    const float* brel  = (const float*)d_in[5];
    const float* wroot = (const float*)d_in[6];
    const float* wproj = (const float*)d_in[7];
    const float* bproj = (const float*)d_in[8];
    float* out = (float*)d_out;

    const int odim = in_sizes[8];
    const int d    = in_sizes[7] / odim;
    const int N    = in_sizes[0] / d;
    const int E    = in_sizes[1] / 2;
    const int B    = out_size / odim;
    const int n    = N / B;
    const int k    = (n + 1) / 2;     // ceil(0.5 * n), RATIO = 0.5
    const int Eg   = E / B;
    const int d4   = d / 4;
    const int nrep4 = 1024 / d4;      // gather replicas (16 for d=256)

    // K1
    int warps = (N + 3) / 4;
    size_t smem1 = (size_t)(2 * d4) * sizeof(float4);
    k_scores<<<(warps * 32 + 255) / 256, 256, smem1>>>(
        (const float4*)x, (const float4*)wrel, (const float4*)wroot, N, d4);

    // K2
    const int pd = d > odim ? d : odim;
    size_t smem2 = (size_t)n * 8                 // keys
                 + (size_t)n * 8                 // p, agg
                 + (size_t)k * 8                 // svals + sidx
                 + (size_t)nrep4 * pd * 4        // part
                 + (size_t)d * 4                 // pooled
                 + 16;                           // cnt + pad
    k_pool<<<B, 1024, smem2>>>(x, ei, brel, wproj, bproj, out,
                               n, k, d, odim, E, Eg, nrep4);
}

// round 7
// speedup vs baseline: 1.5849x; 1.0481x over previous
#include <cuda_runtime.h>

#define MAX_N 65536

__device__ float g_p[MAX_N];    // x . w_rel  per node
__device__ float g_r[MAX_N];    // x . w_root per node

// ---------------------------------------------------------------------------
// Kernel 1: per-node dual dot products. 8 lanes per node (4 nodes/warp),
// weights in shared memory.
// ---------------------------------------------------------------------------
__global__ void k_scores(const float4* __restrict__ x4,
                         const float4* __restrict__ wrel4,
                         const float4* __restrict__ wroot4,
                         int N, int d4) {
    extern __shared__ float4 wsm[];
    int t = threadIdx.x;
    for (int c = t; c < 2 * d4; c += blockDim.x)
        wsm[c] = (c < d4) ? wrel4[c] : wroot4[c - d4];
    __syncthreads();
    const float4* wa = wsm;
    const float4* wb = wsm + d4;

    int warp = (blockIdx.x * blockDim.x + t) >> 5;
    int lane = t & 31;
    int sub  = lane >> 3;
    int l8   = lane & 7;
    int node = warp * 4 + sub;
    if (node >= N) return;

    const float4* xr = x4 + (size_t)node * d4;
    float sp = 0.f, sr = 0.f;
#pragma unroll 8
    for (int c = l8; c < d4; c += 8) {
        float4 xv = xr[c];
        float4 a  = wa[c];
        float4 b  = wb[c];
        sp += xv.x * a.x + xv.y * a.y + xv.z * a.z + xv.w * a.w;
        sr += xv.x * b.x + xv.y * b.y + xv.z * b.z + xv.w * b.w;
    }
#pragma unroll
    for (int o = 4; o; o >>= 1) {
        sp += __shfl_xor_sync(0xffffffffu, sp, o);
        sr += __shfl_xor_sync(0xffffffffu, sr, o);
    }
    if (l8 == 0) {
        g_p[node] = sp;
        g_r[node] = sr;
    }
}

// ---------------------------------------------------------------------------
// Kernel 2 (per-graph, 1024 threads): smem edge aggregation, tanh scores,
// O(n) histogram top-k selection (exact, jax tie-break), float4 gather,
// projection.
// ---------------------------------------------------------------------------
__global__ __launch_bounds__(1024, 1)
void k_pool(const float* __restrict__ x,
            const int* __restrict__ ei,
            const float* __restrict__ brel,
            const float* __restrict__ wproj,
            const float* __restrict__ bproj,
            float* __restrict__ out,
            int n, int k, int d, int odim, int E, int Eg, int nrep4) {
    extern __shared__ unsigned char sm[];
    float* p_s    = (float*)sm;                                  // n
    float* agg_s  = p_s + n;                                     // n
    float* svals  = agg_s + n;                                   // k
    int*   sidx   = (int*)(svals + k);                           // k
    unsigned* hist = (unsigned*)(sidx + k);                      // 256
    unsigned* cgt  = hist + 256;                                 // 256
    uint2* list   = (uint2*)(cgt + 256);                         // n (u, idx)
    float* part   = (float*)(list + n);                          // nrep4 * d
    float* pooled = part + nrep4 * d;                            // d
    int*   ctrl   = (int*)(pooled + d);                          // cnt, cnt2, tb, krem

    const int g    = blockIdx.x;
    const int t    = threadIdx.x;
    const int base = g * n;

    if (t < 4) ctrl[t] = 0;
    for (int b = t; b < 256; b += blockDim.x) hist[b] = 0;
    for (int i = t; i < n; i += blockDim.x) {
        p_s[i]   = g_p[base + i];
        agg_s[i] = 0.f;
    }
    __syncthreads();

    // ---- edge aggregation (graph-local, smem atomics) ----
    {
        const int eb = g * Eg;
        for (int e = t; e < Eg; e += blockDim.x) {
            int s  = ei[eb + e] - base;
            int dd = ei[E + eb + e] - base;
            atomicAdd(&agg_s[dd], p_s[s]);
        }
    }
    __syncthreads();

    // ---- tanh score -> monotone u32 bits + bucket histogram ----
    unsigned myu = 0;
    if (t < n) {
        float s = tanhf(agg_s[t] + brel[0] + g_r[base + t]);
        unsigned u = __float_as_uint(s);
        myu = (u & 0x80000000u) ? ~u : (u | 0x80000000u);
        atomicAdd(&hist[myu >> 24], 1u);
    }
    __syncthreads();

    // ---- suffix counts: cgt[b] = #elements in buckets > b ----
    for (int b = t; b < 256; b += blockDim.x) {
        unsigned s = 0;
        for (int j = b + 1; j < 256; j++) s += hist[j];
        cgt[b] = s;
        // threshold bucket: cgt[b] < k <= cgt[b] + hist[b]
        if (s < (unsigned)k && (unsigned)k <= s + hist[b]) {
            ctrl[2] = b;                 // tb
            ctrl[3] = k - (int)s;        // krem
        }
    }
    __syncthreads();

    const int tb   = ctrl[2];
    const int krem = ctrl[3];

    // ---- emit: buckets > tb selected outright; bucket == tb to fine list ----
    if (t < n) {
        int b = (int)(myu >> 24);
        if (b > tb) {
            int pos = atomicAdd(&ctrl[0], 1);
            unsigned fu = (myu & 0x80000000u) ? (myu & 0x7fffffffu) : ~myu;
            svals[pos] = __uint_as_float(fu);
            sidx[pos]  = t;
        } else if (b == tb) {
            int pos = atomicAdd(&ctrl[1], 1);
            list[pos] = make_uint2(myu, (unsigned)t);
        }
    }
    __syncthreads();

    // ---- fine rank within threshold bucket (m usually small) ----
    {
        const int m = ctrl[1];
        if (t < m) {
            uint2 me = list[t];
            int r = 0;
            for (int l = 0; l < m; l++) {
                uint2 o = list[l];
                r += (o.x > me.x) || (o.x == me.x && o.y < me.y);
            }
            if (r < krem) {
                int pos = atomicAdd(&ctrl[0], 1);
                unsigned fu = (me.x & 0x80000000u) ? (me.x & 0x7fffffffu) : ~me.x;
                svals[pos] = __uint_as_float(fu);
                sidx[pos]  = (int)me.y;
            }
        }
    }
    __syncthreads();

    // ---- weighted mean: float4 gather, nrep4 replicas over nodes ----
    {
        const int d4   = d >> 2;
        const int col4 = t % d4;
        const int rep  = t / d4;
        const int per  = (k + nrep4 - 1) / nrep4;
        const int j0   = rep * per;
        const int j1   = min(j0 + per, k);
        const float4* x4 = (const float4*)x;
        float4 a0 = {0,0,0,0}, a1 = {0,0,0,0}, a2 = {0,0,0,0}, a3 = {0,0,0,0};
        int j = j0;
        for (; j + 4 <= j1; j += 4) {
            float v0 = svals[j], v1 = svals[j+1], v2 = svals[j+2], v3 = svals[j+3];
            int   r0 = sidx[j],  r1 = sidx[j+1],  r2 = sidx[j+2],  r3 = sidx[j+3];
            float4 q0 = x4[(size_t)(base + r0) * d4 + col4];
            float4 q1 = x4[(size_t)(base + r1) * d4 + col4];
            float4 q2 = x4[(size_t)(base + r2) * d4 + col4];
            float4 q3 = x4[(size_t)(base + r3) * d4 + col4];
            a0.x += v0*q0.x; a0.y += v0*q0.y; a0.z += v0*q0.z; a0.w += v0*q0.w;
            a1.x += v1*q1.x; a1.y += v1*q1.y; a1.z += v1*q1.z; a1.w += v1*q1.w;
            a2.x += v2*q2.x; a2.y += v2*q2.y; a2.z += v2*q2.z; a2.w += v2*q2.w;
            a3.x += v3*q3.x; a3.y += v3*q3.y; a3.z += v3*q3.z; a3.w += v3*q3.w;
        }
        for (; j < j1; j++) {
            float v = svals[j];
            float4 q = x4[(size_t)(base + sidx[j]) * d4 + col4];
            a0.x += v*q.x; a0.y += v*q.y; a0.z += v*q.z; a0.w += v*q.w;
        }
        float4 s;
        s.x = a0.x + a1.x + a2.x + a3.x;
        s.y = a0.y + a1.y + a2.y + a3.y;
        s.z = a0.z + a1.z + a2.z + a3.z;
        s.w = a0.w + a1.w + a2.w + a3.w;
        ((float4*)part)[rep * d4 + col4] = s;
    }
    __syncthreads();

    if (t < d) {
        float s = 0.f;
        for (int rr = 0; rr < nrep4; rr++) s += part[rr * d + t];
        pooled[t] = s / (float)k;
    }
    __syncthreads();

    // ---- projection ----
    {
        const int o    = t % odim;
        const int p    = t / odim;
        const int nrep = blockDim.x / odim;
        const int per  = (d + nrep - 1) / nrep;
        const int d0   = p * per;
        const int d1   = min(d0 + per, d);
        float acc = 0.f;
        int dd = d0;
        for (; dd + 8 <= d1; dd += 8) {
#pragma unroll
            for (int u = 0; u < 8; u++)
                acc += pooled[dd + u] * wproj[(size_t)(dd + u) * odim + o];
        }
        for (; dd < d1; dd++)
            acc += pooled[dd] * wproj[(size_t)dd * odim + o];
        part[p * odim + o] = acc;
    }
    __syncthreads();

    if (t < odim) {
        const int nrep = blockDim.x / odim;
        float s = bproj[t];
        for (int rr = 0; rr < nrep; rr++) s += part[rr * odim + t];
        out[(size_t)g * odim + t] = s;
    }
}

// ---------------------------------------------------------------------------
extern "C" void kernel_launch(void* const* d_in, const int* in_sizes, int n_in,
                              void* d_out, int out_size) {
    const float* x     = (const float*)d_in[0];
    const int*   ei    = (const int*)d_in[1];
    const float* wrel  = (const float*)d_in[4];
    const float* brel  = (const float*)d_in[5];
    const float* wroot = (const float*)d_in[6];
    const float* wproj = (const float*)d_in[7];
    const float* bproj = (const float*)d_in[8];
    float* out = (float*)d_out;

    const int odim = in_sizes[8];
    const int d    = in_sizes[7] / odim;
    const int N    = in_sizes[0] / d;
    const int E    = in_sizes[1] / 2;
    const int B    = out_size / odim;
    const int n    = N / B;
    const int k    = (n + 1) / 2;     // ceil(0.5 * n), RATIO = 0.5
    const int Eg   = E / B;
    const int d4   = d / 4;
    const int nrep4 = 1024 / d4;

    // K1
    int warps = (N + 3) / 4;
    size_t smem1 = (size_t)(2 * d4) * sizeof(float4);
    k_scores<<<(warps * 32 + 255) / 256, 256, smem1>>>(
        (const float4*)x, (const float4*)wrel, (const float4*)wroot, N, d4);

    // K2
    const int pd = d > odim ? d : odim;
    size_t smem2 = (size_t)n * 8                 // p, agg
                 + (size_t)k * 8                 // svals + sidx
                 + 512 * 4                       // hist + cgt
                 + (size_t)n * 8                 // fine list
                 + (size_t)nrep4 * pd * 4        // part
                 + (size_t)d * 4                 // pooled
                 + 32;                           // ctrl + pad
    k_pool<<<B, 1024, smem2>>>(x, ei, brel, wproj, bproj, out,
                               n, k, d, odim, E, Eg, nrep4);
}